// round 7
// baseline (speedup 1.0000x reference)
#include <cuda_runtime.h>
#include <cuda_bf16.h>

#define TT    65536
#define BB    4
#define W     16
#define NL    18
#define TILE  384        // ts per tile (= NTH*3)
#define NTH   128
#define TPB   171        // tiles per batch = ceil(65536/384)
#define NTILES (TPB*BB)  // 684
#define GRID  444        // 3 CTAs/SM * 148 SMs

typedef unsigned long long u64;

// hidden state, channel-major: [b][ch][T]
__device__ float g_h0[(size_t)BB * W * TT];
__device__ float g_h1[(size_t)BB * W * TT];

__device__ __forceinline__ u64 pk2(float x){ u64 r; asm("mov.b64 %0,{%1,%1};":"=l"(r):"f"(x)); return r; }
__device__ __forceinline__ u64 pk(float lo, float hi){ u64 r; asm("mov.b64 %0,{%1,%2};":"=l"(r):"f"(lo),"f"(hi)); return r; }
__device__ __forceinline__ void unpk(u64 v, float& lo, float& hi){ asm("mov.b64 {%0,%1},%2;":"=f"(lo),"=f"(hi):"l"(v)); }
__device__ __forceinline__ u64 fma2(u64 a, u64 b, u64 c){ u64 d; asm("fma.rn.f32x2 %0,%1,%2,%3;":"=l"(d):"l"(a),"l"(b),"l"(c)); return d; }
__device__ __forceinline__ u64 mul2(u64 a, u64 b){ u64 d; asm("mul.rn.f32x2 %0,%1,%2;":"=l"(d):"l"(a),"l"(b)); return d; }
__device__ __forceinline__ u64 add2(u64 a, u64 b){ u64 d; asm("add.rn.f32x2 %0,%1,%2;":"=l"(d):"l"(a),"l"(b)); return d; }
__device__ __forceinline__ float rcpf(float x){ float r; asm("rcp.approx.f32 %0,%1;":"=f"(r):"f"(x)); return r; }

#define ABS2 0x7FFFFFFF7FFFFFFFull
#define ONE2 0x3F8000003F800000ull

// z = softsign(f)*softsign(g) = f*g / ((1+|f|)(1+|g|)), packed over 2 channels
__device__ __forceinline__ u64 ssz(u64 f, u64 g){
    u64 df = add2(f & ABS2, ONE2);
    u64 dg = add2(g & ABS2, ONE2);
    u64 dd = mul2(df, dg);
    float dl, dh; unpk(dd, dl, dh);
    u64 rr = pk(rcpf(dl), rcpf(dh));
    return mul2(mul2(f, g), rr);
}

__global__ void start_kernel(const float* __restrict__ x,
                             const float* __restrict__ sw,
                             float* __restrict__ out) {
    int idx = blockIdx.x * blockDim.x + threadIdx.x;  // over B*T
    if (idx < BB * TT) {
        int b = idx >> 16, t = idx & (TT - 1);
        float xv = x[idx];
        #pragma unroll
        for (int o = 0; o < W; o++)
            g_h0[(((size_t)b * W + o) << 16) + t] = sw[o] * xv;
        out[idx] = 0.f;
    }
}

// smem layout (floats):
//  [0    :1536)  conv+gate weights, ((k*16+i)*32 + half*16 + o); half0=f, half1=g
//  [1536 :1792)  res weights transposed rsm[i][o]
//  [1792 :1808)  mixer, [1808:1824) conv bias, [1824:1840) gate bias, [1840:1856) res bias
__global__ __launch_bounds__(NTH, 3)
void layer7_kernel(const float* __restrict__ cw, const float* __restrict__ cb,
                   const float* __restrict__ gw, const float* __restrict__ gb,
                   const float* __restrict__ rw, const float* __restrict__ rb,
                   const float* __restrict__ mix, float* __restrict__ out,
                   int li, int d, int last)
{
    __shared__ float sh[1856];
    const float* hin  = (li & 1) ? g_h1 : g_h0;
    float*       hout = (li & 1) ? g_h0 : g_h1;
    const int tid = threadIdx.x;

    // ---- weight prep (once per CTA) ----
    for (int w = tid; w < 1536; w += NTH) {
        int k = w >> 9, rem = w & 511;
        int i = rem >> 5, half = (rem >> 4) & 1, o = rem & 15;
        const float* src = half ? gw : cw;
        sh[w] = src[li * 768 + o * 48 + i * 3 + k];
    }
    for (int w = tid; w < 256; w += NTH) {
        int i = w >> 4, o = w & 15;
        sh[1536 + w] = last ? 0.f : rw[li * 256 + o * 16 + i];
    }
    if (tid < 16) {
        sh[1792 + tid] = mix[li * 16 + tid];
        sh[1808 + tid] = cb[li * 16 + tid];
        sh[1824 + tid] = gb[li * 16 + tid];
        sh[1840 + tid] = last ? 0.f : rb[li * 16 + tid];
    }
    __syncthreads();

    // ---- persistent tile loop (no further syncs) ----
    for (int tile = blockIdx.x; tile < NTILES; tile += GRID) {
        const int b  = tile / TPB;
        const int t0 = (tile - b * TPB) * TILE;
        const int ts0 = t0 + tid;                 // m-th ts = ts0 + 128*m
        const bool v2 = (ts0 + 256) < TT;         // only m=2 can spill past T

        const float* hb = hin + ((size_t)b * W << 16);

        // ---- conv ----
        u64 f[3][8], g[3][8];
        {
            const u64* bp = (const u64*)(sh + 1808);
            #pragma unroll
            for (int p = 0; p < 8; p++) {
                u64 cbv = bp[p], gbv = bp[8 + p];
                #pragma unroll
                for (int m = 0; m < 3; m++) { f[m][p] = cbv; g[m][p] = gbv; }
            }
        }

        #pragma unroll 1
        for (int k = 0; k < 3; k++) {
            const int off = ts0 - (2 - k) * d;    // tap t-index, m=0
            const bool p0 = off >= 0;
            const bool p1 = (off + 128) >= 0;
            const bool p2 = ((off + 256) >= 0) & v2;
            const float* tp = hb + (ptrdiff_t)off;
            #pragma unroll 4
            for (int i = 0; i < 16; i++) {
                const float* row = tp + ((ptrdiff_t)i << 16);
                float hv0 = p0 ? row[0]   : 0.f;
                float hv1 = p1 ? row[128] : 0.f;
                float hv2 = p2 ? row[256] : 0.f;
                u64 hp0 = pk2(hv0), hp1 = pk2(hv1), hp2 = pk2(hv2);
                const ulonglong2* wp = (const ulonglong2*)(sh) + (k * 16 + i) * 8;
                #pragma unroll
                for (int q = 0; q < 4; q++) {
                    ulonglong2 wf = wp[q];
                    ulonglong2 wg = wp[4 + q];
                    f[0][2*q]   = fma2(wf.x, hp0, f[0][2*q]);
                    f[0][2*q+1] = fma2(wf.y, hp0, f[0][2*q+1]);
                    f[1][2*q]   = fma2(wf.x, hp1, f[1][2*q]);
                    f[1][2*q+1] = fma2(wf.y, hp1, f[1][2*q+1]);
                    f[2][2*q]   = fma2(wf.x, hp2, f[2][2*q]);
                    f[2][2*q+1] = fma2(wf.y, hp2, f[2][2*q+1]);
                    g[0][2*q]   = fma2(wg.x, hp0, g[0][2*q]);
                    g[0][2*q+1] = fma2(wg.y, hp0, g[0][2*q+1]);
                    g[1][2*q]   = fma2(wg.x, hp1, g[1][2*q]);
                    g[1][2*q+1] = fma2(wg.y, hp1, g[1][2*q+1]);
                    g[2][2*q]   = fma2(wg.x, hp2, g[2][2*q]);
                    g[2][2*q+1] = fma2(wg.y, hp2, g[2][2*q+1]);
                }
            }
        }

        // ---- gated activation (z overwrites f) ----
        #pragma unroll
        for (int m = 0; m < 3; m++)
            #pragma unroll
            for (int p = 0; p < 8; p++)
                f[m][p] = ssz(f[m][p], g[m][p]);

        // ---- mixer ----
        {
            const u64* mp = (const u64*)(sh + 1792);
            #pragma unroll
            for (int m = 0; m < 3; m++) {
                u64 acc = mul2(mp[0], f[m][0]);
                #pragma unroll
                for (int p = 1; p < 8; p++) acc = fma2(mp[p], f[m][p], acc);
                float a, c; unpk(acc, a, c);
                if (m < 2 || v2)
                    out[((size_t)b << 16) + ts0 + 128 * m] += a + c;
            }
        }

        // ---- residual + write next h (channel-major coalesced I/O) ----
        if (!last) {
            const u64* rbp = (const u64*)(sh + 1840);
            u64 hn[3][8];
            #pragma unroll
            for (int m = 0; m < 3; m++) {
                if (m < 2 || v2) {
                    const float* hp = hb + ts0 + 128 * m;
                    #pragma unroll
                    for (int p = 0; p < 8; p++) {
                        float a = hp[(ptrdiff_t)(2*p)     << 16];
                        float c = hp[(ptrdiff_t)(2*p + 1) << 16];
                        hn[m][p] = add2(pk(a, c), rbp[p]);
                    }
                } else {
                    #pragma unroll
                    for (int p = 0; p < 8; p++) hn[m][p] = 0ull;
                }
            }
            #pragma unroll 4
            for (int i = 0; i < 16; i++) {
                const ulonglong2* rp = (const ulonglong2*)(sh + 1536) + i * 4;
                ulonglong2 r0 = rp[0], r1 = rp[1], r2 = rp[2], r3 = rp[3];
                #pragma unroll
                for (int m = 0; m < 3; m++) {
                    float lo, hi; unpk(f[m][i >> 1], lo, hi);
                    u64 zp = pk2((i & 1) ? hi : lo);
                    hn[m][0] = fma2(r0.x, zp, hn[m][0]);
                    hn[m][1] = fma2(r0.y, zp, hn[m][1]);
                    hn[m][2] = fma2(r1.x, zp, hn[m][2]);
                    hn[m][3] = fma2(r1.y, zp, hn[m][3]);
                    hn[m][4] = fma2(r2.x, zp, hn[m][4]);
                    hn[m][5] = fma2(r2.y, zp, hn[m][5]);
                    hn[m][6] = fma2(r3.x, zp, hn[m][6]);
                    hn[m][7] = fma2(r3.y, zp, hn[m][7]);
                }
            }
            float* ho = hout + ((size_t)b * W << 16) + ts0;
            #pragma unroll
            for (int m = 0; m < 3; m++) {
                if (m < 2 || v2) {
                    #pragma unroll
                    for (int p = 0; p < 8; p++) {
                        float lo, hi; unpk(hn[m][p], lo, hi);
                        ho[((ptrdiff_t)(2*p)     << 16) + 128 * m] = lo;
                        ho[((ptrdiff_t)(2*p + 1) << 16) + 128 * m] = hi;
                    }
                }
            }
        }
    }
}

extern "C" void kernel_launch(void* const* d_in, const int* in_sizes, int n_in,
                              void* d_out, int out_size) {
    const float* x   = (const float*)d_in[0];
    const float* sw  = (const float*)d_in[1];
    const float* cw  = (const float*)d_in[2];
    const float* cb  = (const float*)d_in[3];
    const float* gw  = (const float*)d_in[4];
    const float* gb  = (const float*)d_in[5];
    const float* rw  = (const float*)d_in[6];
    const float* rb  = (const float*)d_in[7];
    const float* mix = (const float*)d_in[8];
    float* out = (float*)d_out;

    static const int dil[NL] = {1,2,4,8,16,32,64,128,256,
                                1,2,4,8,16,32,64,128,256};

    start_kernel<<<(BB * TT + 255) / 256, 256>>>(x, sw, out);

    for (int li = 0; li < NL; li++) {
        layer7_kernel<<<GRID, NTH>>>(
            cw, cb, gw, gb, rw, rb, mix, out,
            li, dil[li], (li == NL - 1) ? 1 : 0);
    }
}

// round 8
// speedup vs baseline: 1.1701x; 1.1701x over previous
#include <cuda_runtime.h>
#include <cuda_bf16.h>

#define TT   65536
#define BB   4
#define W    16
#define NL   18
#define TILE 512
#define NTH  256
#define HOFF 1856

typedef unsigned long long u64;

// hidden state ping-pong, layout [b][t][ch]
__device__ float g_h0[(size_t)BB * TT * W];
__device__ float g_h1[(size_t)BB * TT * W];

__device__ __forceinline__ u64 pk2(float x){ u64 r; asm("mov.b64 %0,{%1,%1};":"=l"(r):"f"(x)); return r; }
__device__ __forceinline__ u64 pk(float lo, float hi){ u64 r; asm("mov.b64 %0,{%1,%2};":"=l"(r):"f"(lo),"f"(hi)); return r; }
__device__ __forceinline__ void unpk(u64 v, float& lo, float& hi){ asm("mov.b64 {%0,%1},%2;":"=f"(lo),"=f"(hi):"l"(v)); }
__device__ __forceinline__ u64 fma2(u64 a, u64 b, u64 c){ u64 d; asm("fma.rn.f32x2 %0,%1,%2,%3;":"=l"(d):"l"(a),"l"(b),"l"(c)); return d; }
__device__ __forceinline__ u64 mul2(u64 a, u64 b){ u64 d; asm("mul.rn.f32x2 %0,%1,%2;":"=l"(d):"l"(a),"l"(b)); return d; }
__device__ __forceinline__ u64 add2(u64 a, u64 b){ u64 d; asm("add.rn.f32x2 %0,%1,%2;":"=l"(d):"l"(a),"l"(b)); return d; }
__device__ __forceinline__ float rcpf(float x){ float r; asm("rcp.approx.f32 %0,%1;":"=f"(r):"f"(x)); return r; }

#define ABS2 0x7FFFFFFF7FFFFFFFull
#define ONE2 0x3F8000003F800000ull

__device__ __forceinline__ u64 ssz(u64 f, u64 g){
    u64 df = add2(f & ABS2, ONE2);
    u64 dg = add2(g & ABS2, ONE2);
    u64 dd = mul2(df, dg);
    float dl, dh; unpk(dd, dl, dh);
    u64 rr = pk(rcpf(dl), rcpf(dh));
    return mul2(mul2(f, g), rr);
}

__global__ void start_kernel(const float* __restrict__ x,
                             const float* __restrict__ sw,
                             float* __restrict__ out) {
    int idx = blockIdx.x * blockDim.x + threadIdx.x;
    if (idx < BB * TT) {
        float xv = x[idx];
        #pragma unroll
        for (int o = 0; o < W; o++) g_h0[(size_t)idx * W + o] = sw[o] * xv;
        out[idx] = 0.f;
    }
}

// Row stride padded: R % 8 == 2 (conflict-free transpose store + residual reads)
__host__ __device__ __forceinline__ int padR(int d) {
    int R = TILE + 2 * d;
    R += ((2 - (R & 7)) + 8) & 7;
    return R;
}

// smem (floats):
//  [0:1536)     conv+gate weights: ((k*16+i)*2+cg)*16 + half*8 + j ; o=8cg+j; half0=f,1=g
//  [1536:1792)  res weights: (i*2+cg)*8 + j  = rw[o=8cg+j][i]
//  [1792:1808)  mixer  [1808:1824) conv bias [1824:1840) gate bias [1840:1856) res bias
//  [1856:...)   hT[ch][R] channel-major tile
__global__ __launch_bounds__(NTH, 2)
void layer8_kernel(const float* __restrict__ cw, const float* __restrict__ cb,
                   const float* __restrict__ gw, const float* __restrict__ gb,
                   const float* __restrict__ rw, const float* __restrict__ rb,
                   const float* __restrict__ mix, float* __restrict__ out,
                   int li, int d, int last)
{
    extern __shared__ float sh[];
    const float* hin  = (li & 1) ? g_h1 : g_h0;
    float*       hout = (li & 1) ? g_h0 : g_h1;
    const int b   = blockIdx.y;
    const int t0  = blockIdx.x * TILE;
    const int tid = threadIdx.x;
    const int R   = padR(d);
    float* hT = sh + HOFF;

    // ---- weight prep ----
    for (int w = tid; w < 1536; w += NTH) {
        int k = w >> 9, rem = w & 511;
        int pair = rem >> 4, w16 = rem & 15;
        int i = pair >> 1, cgx = pair & 1;
        int half = w16 >> 3, j = w16 & 7;
        const float* src = half ? gw : cw;
        sh[w] = src[li * 768 + (8 * cgx + j) * 48 + i * 3 + k];
    }
    for (int w = tid; w < 256; w += NTH) {
        int i = w >> 4, rem = w & 15;
        int cgx = rem >> 3, j = rem & 7;
        sh[1536 + w] = last ? 0.f : rw[li * 256 + (8 * cgx + j) * 16 + i];
    }
    if (tid < 16) {
        sh[1792 + tid] = mix[li * 16 + tid];
        sh[1808 + tid] = cb[li * 16 + tid];
        sh[1824 + tid] = gb[li * 16 + tid];
        sh[1840 + tid] = last ? 0.f : rb[li * 16 + tid];
    }

    // ---- h tile load, transposing [t][ch] -> [ch][t] ----
    {
        const int n4 = (TILE + 2 * d) * 4;
        for (int idx = tid; idx < n4; idx += NTH) {
            int r = idx >> 2, c = idx & 3;
            int gt = t0 - 2 * d + r;
            float4 v = make_float4(0.f, 0.f, 0.f, 0.f);
            if (gt >= 0)
                v = *(const float4*)(hin + ((size_t)b * TT + gt) * W + 4 * c);
            hT[(4 * c + 0) * R + r] = v.x;
            hT[(4 * c + 1) * R + r] = v.y;
            hT[(4 * c + 2) * R + r] = v.z;
            hT[(4 * c + 3) * R + r] = v.w;
        }
    }
    __syncthreads();

    // ---- lane mapping: 16 ts-lanes x 2 channel-groups; 4 slots of 16 ts ----
    const int lane = tid & 31;
    const int warp = tid >> 5;
    const int ct   = lane & 15;
    const int cg   = lane >> 4;          // 0: ch 0-7, 1: ch 8-15
    const int tb   = warp * 64 + ct;     // local ts of slot 0

    // ---- conv: f[s][jp], g[s][jp] cover channels (8cg+2jp, 8cg+2jp+1) ----
    u64 f[4][4], g[4][4];
    {
        const u64* cbp = (const u64*)(sh + 1808) + cg * 4;
        const u64* gbp = (const u64*)(sh + 1824) + cg * 4;
        #pragma unroll
        for (int jp = 0; jp < 4; jp++) {
            u64 cv = cbp[jp], gv = gbp[jp];
            #pragma unroll
            for (int s = 0; s < 4; s++) { f[s][jp] = cv; g[s][jp] = gv; }
        }
    }

    #pragma unroll 1
    for (int k = 0; k < 3; k++) {
        const float* tp = hT + tb + k * d;
        #pragma unroll 4
        for (int i = 0; i < 16; i++) {
            const float* row = tp + i * R;
            u64 hp0 = pk2(row[0]);
            u64 hp1 = pk2(row[16]);
            u64 hp2 = pk2(row[32]);
            u64 hp3 = pk2(row[48]);
            const ulonglong2* wp =
                (const ulonglong2*)sh + ((k * 16 + i) * 2 + cg) * 4;
            ulonglong2 wf0 = wp[0], wf1 = wp[1];   // f: ch pairs 0-3 of group
            ulonglong2 wg0 = wp[2], wg1 = wp[3];   // g
            f[0][0] = fma2(wf0.x, hp0, f[0][0]);
            f[0][1] = fma2(wf0.y, hp0, f[0][1]);
            f[0][2] = fma2(wf1.x, hp0, f[0][2]);
            f[0][3] = fma2(wf1.y, hp0, f[0][3]);
            g[0][0] = fma2(wg0.x, hp0, g[0][0]);
            g[0][1] = fma2(wg0.y, hp0, g[0][1]);
            g[0][2] = fma2(wg1.x, hp0, g[0][2]);
            g[0][3] = fma2(wg1.y, hp0, g[0][3]);
            f[1][0] = fma2(wf0.x, hp1, f[1][0]);
            f[1][1] = fma2(wf0.y, hp1, f[1][1]);
            f[1][2] = fma2(wf1.x, hp1, f[1][2]);
            f[1][3] = fma2(wf1.y, hp1, f[1][3]);
            g[1][0] = fma2(wg0.x, hp1, g[1][0]);
            g[1][1] = fma2(wg0.y, hp1, g[1][1]);
            g[1][2] = fma2(wg1.x, hp1, g[1][2]);
            g[1][3] = fma2(wg1.y, hp1, g[1][3]);
            f[2][0] = fma2(wf0.x, hp2, f[2][0]);
            f[2][1] = fma2(wf0.y, hp2, f[2][1]);
            f[2][2] = fma2(wf1.x, hp2, f[2][2]);
            f[2][3] = fma2(wf1.y, hp2, f[2][3]);
            g[2][0] = fma2(wg0.x, hp2, g[2][0]);
            g[2][1] = fma2(wg0.y, hp2, g[2][1]);
            g[2][2] = fma2(wg1.x, hp2, g[2][2]);
            g[2][3] = fma2(wg1.y, hp2, g[2][3]);
            f[3][0] = fma2(wf0.x, hp3, f[3][0]);
            f[3][1] = fma2(wf0.y, hp3, f[3][1]);
            f[3][2] = fma2(wf1.x, hp3, f[3][2]);
            f[3][3] = fma2(wf1.y, hp3, f[3][3]);
            g[3][0] = fma2(wg0.x, hp3, g[3][0]);
            g[3][1] = fma2(wg0.y, hp3, g[3][1]);
            g[3][2] = fma2(wg1.x, hp3, g[3][2]);
            g[3][3] = fma2(wg1.y, hp3, g[3][3]);
        }
    }

    // ---- epilogue: two phases of 2 slots each (caps live registers) ----
    const u64* mp  = (const u64*)(sh + 1792);
    const u64* rbp = (const u64*)(sh + 1840) + cg * 4;

    #pragma unroll
    for (int ph = 0; ph < 2; ph++) {
        float zf[2][16];                 // full z, unpacked, per slot in phase
        #pragma unroll
        for (int sl = 0; sl < 2; sl++) {
            const int s = 2 * ph + sl;
            u64 z[4], zo[4];
            #pragma unroll
            for (int jp = 0; jp < 4; jp++) {
                z[jp]  = ssz(f[s][jp], g[s][jp]);
                zo[jp] = __shfl_xor_sync(0xFFFFFFFFu, z[jp], 16);
            }
            // zl = ch0-7 pairs, zh = ch8-15 pairs
            u64 zl[4], zh[4];
            #pragma unroll
            for (int jp = 0; jp < 4; jp++) {
                zl[jp] = cg ? zo[jp] : z[jp];
                zh[jp] = cg ? z[jp]  : zo[jp];
            }
            // mixer
            u64 acc = mul2(mp[0], zl[0]);
            acc = fma2(mp[1], zl[1], acc);
            acc = fma2(mp[2], zl[2], acc);
            acc = fma2(mp[3], zl[3], acc);
            acc = fma2(mp[4], zh[0], acc);
            acc = fma2(mp[5], zh[1], acc);
            acc = fma2(mp[6], zh[2], acc);
            acc = fma2(mp[7], zh[3], acc);
            float a, c; unpk(acc, a, c);
            if (cg == 0)
                out[(size_t)b * TT + t0 + tb + 16 * s] += a + c;
            // unpack z to floats for residual
            #pragma unroll
            for (int jp = 0; jp < 4; jp++) {
                unpk(zl[jp], zf[sl][2*jp],     zf[sl][2*jp + 1]);
                unpk(zh[jp], zf[sl][8 + 2*jp], zf[sl][9 + 2*jp]);
            }
        }

        if (!last) {
            u64 hn[2][4];
            #pragma unroll
            for (int sl = 0; sl < 2; sl++) {
                const int rr = 2 * d + tb + 16 * (2 * ph + sl);
                #pragma unroll
                for (int jp = 0; jp < 4; jp++) {
                    float a = hT[(8 * cg + 2 * jp)     * R + rr];
                    float c = hT[(8 * cg + 2 * jp + 1) * R + rr];
                    hn[sl][jp] = add2(pk(a, c), rbp[jp]);
                }
            }
            #pragma unroll 4
            for (int i = 0; i < 16; i++) {
                const ulonglong2* rp =
                    (const ulonglong2*)(sh + 1536) + (i * 2 + cg) * 2;
                ulonglong2 r01 = rp[0], r23 = rp[1];
                #pragma unroll
                for (int sl = 0; sl < 2; sl++) {
                    u64 zi = pk2(zf[sl][i]);
                    hn[sl][0] = fma2(r01.x, zi, hn[sl][0]);
                    hn[sl][1] = fma2(r01.y, zi, hn[sl][1]);
                    hn[sl][2] = fma2(r23.x, zi, hn[sl][2]);
                    hn[sl][3] = fma2(r23.y, zi, hn[sl][3]);
                }
            }
            #pragma unroll
            for (int sl = 0; sl < 2; sl++) {
                const int s = 2 * ph + sl;
                ulonglong2* o = (ulonglong2*)(hout +
                    ((size_t)b * TT + t0 + tb + 16 * s) * W + 8 * cg);
                o[0] = make_ulonglong2(hn[sl][0], hn[sl][1]);
                o[1] = make_ulonglong2(hn[sl][2], hn[sl][3]);
            }
        }
    }
}

extern "C" void kernel_launch(void* const* d_in, const int* in_sizes, int n_in,
                              void* d_out, int out_size) {
    const float* x   = (const float*)d_in[0];
    const float* sw  = (const float*)d_in[1];
    const float* cw  = (const float*)d_in[2];
    const float* cb  = (const float*)d_in[3];
    const float* gw  = (const float*)d_in[4];
    const float* gb  = (const float*)d_in[5];
    const float* rw  = (const float*)d_in[6];
    const float* rb  = (const float*)d_in[7];
    const float* mix = (const float*)d_in[8];
    float* out = (float*)d_out;

    static const int dil[NL] = {1,2,4,8,16,32,64,128,256,
                                1,2,4,8,16,32,64,128,256};

    const int max_smem = (HOFF + W * padR(256)) * (int)sizeof(float);
    cudaFuncSetAttribute(layer8_kernel,
                         cudaFuncAttributeMaxDynamicSharedMemorySize, max_smem);

    start_kernel<<<(BB * TT + 255) / 256, 256>>>(x, sw, out);

    dim3 grid(TT / TILE, BB);
    for (int li = 0; li < NL; li++) {
        int d = dil[li];
        int smem = (HOFF + W * padR(d)) * (int)sizeof(float);
        layer8_kernel<<<grid, NTH, smem>>>(
            cw, cb, gw, gb, rw, rb, mix, out,
            li, d, (li == NL - 1) ? 1 : 0);
    }
}